// round 14
// baseline (speedup 1.0000x reference)
#include <cuda_runtime.h>
#include <cuda_fp16.h>
#include <cstdint>

// Problem constants
#define BN 32
#define LN 32768
#define DN 128
#define PN 4095   // (L-K)/STRIDE + 1

// ---------------------------------------------------------------------------
// Pre-packed B (fp16), fragment-linear layout:
// half index = ((c*4 + ks)*16 + nb)*128 + l*4 + j*2 + e
// value = W[n][kg], n = nb*8+g, kg = c*64 + ks*16 + 2q + 8j + e
// W[n][kg] = conv_w[n*512 + (kg%32)*16 + (kg/32)]
// ---------------------------------------------------------------------------
__device__ __half g_Bh[65536];   // 128 KB

__global__ void pack_w_kernel(const float* __restrict__ w) {
    int idx = blockIdx.x * blockDim.x + threadIdx.x;  // 0..65535
    int e  = idx & 1;
    int j  = (idx >> 1) & 1;
    int l  = (idx >> 2) & 31;
    int nb = (idx >> 7) & 15;
    int ks = (idx >> 11) & 3;
    int c  = idx >> 13;
    int n  = nb * 8 + (l >> 2);
    int kg = c * 64 + ks * 16 + 2 * (l & 3) + 8 * j + e;
    g_Bh[idx] = __float2half_rn(w[n * 512 + (kg & 31) * 16 + (kg >> 5)]);
}

__device__ __forceinline__ uint32_t pack_h2(float x, float y) {
    uint32_t r;
    asm("{ .reg .f16 lo, hi;\n\t"
        "cvt.rn.f16.f32 lo, %1;\n\t"
        "cvt.rn.f16.f32 hi, %2;\n\t"
        "mov.b32 %0, {lo, hi}; }"
        : "=r"(r) : "f"(x), "f"(y));
    return r;
}

__device__ __forceinline__ void mma_f16(float c[4], const uint32_t a[4],
                                        uint32_t b0, uint32_t b1) {
    asm volatile(
        "mma.sync.aligned.m16n8k16.row.col.f32.f16.f16.f32 "
        "{%0,%1,%2,%3}, {%4,%5,%6,%7}, {%8,%9}, {%0,%1,%2,%3};\n"
        : "+f"(c[0]), "+f"(c[1]), "+f"(c[2]), "+f"(c[3])
        : "r"(a[0]), "r"(a[1]), "r"(a[2]), "r"(a[3]), "r"(b0), "r"(b1));
}

__device__ __forceinline__ uint32_t smem_u32(const void* p) {
    uint32_t a;
    asm("{ .reg .u64 t; cvta.to.shared.u64 t, %1; cvt.u32.u64 %0, t; }"
        : "=r"(a) : "l"(p));
    return a;
}

// A buffers: 2, each 129 rows x 64 halfs, pitch 144B.
// Chunk pair (p, p+4) shares tile p: chunk p reads rows 0-127, p+4 rows 1-128.
#define AROW  144
#define ABUF  (129 * AROW)      // 18576 B
#define BTILE 16384             // fragment-linear B chunk

// SMEM offsets (dynamic shared)
#define OFF_A    0
#define OFF_B    (2 * ABUF)                  // 37152
#define OFF_MEDS (OFF_B + 4 * BTILE)         // 102688
#define OFF_BIAS (OFF_MEDS + 512)
#define OFF_DIV  (OFF_BIAS + 512)
#define SMEM_TOTAL (OFF_DIV + 256)           // 103968

// CTA: 128 patches x 128 D, 512 threads = 16 warps (4 m x 4 n),
// warp tile 32(m) x 32(n), acc = 32 regs -> 2 CTAs/SM = 32 warps/SM.
// K = 512 as 4 pairs of chunks (c, c+4).  A: 2 buffers (overlap reuse).
// B: 4 stages; pair p uses stages (p%2)*2..+1 (pair p+2 aliases pair p);
// pair p+1's group is committed in iter p AFTER the barrier retiring p-1.
__global__ __launch_bounds__(512, 2) void patch_encoder_kernel(
    const float* __restrict__ x,     // (B, L, M)
    const float* __restrict__ ts,    // (B, L)
    const float* __restrict__ bias,  // (D,)
    float* __restrict__ out)         // (B, P, D)
{
    extern __shared__ __align__(16) unsigned char smem[];
    const uint32_t sbase = smem_u32(smem);

    const int tid  = threadIdx.x;
    const int b    = blockIdx.y;
    const int p0   = blockIdx.x * 128;
    const int wid  = tid >> 5;
    const int lane = tid & 31;
    const int wm   = wid & 3;     // m offset wm*32
    const int wn   = wid >> 2;    // n offset wn*32  (0..3)
    const int g    = lane >> 2;
    const int q    = lane & 3;

    float* meds  = (float*)(smem + OFF_MEDS);
    float* sbias = (float*)(smem + OFF_BIAS);
    float* sdiv  = (float*)(smem + OFF_DIV);

    if (tid < 128) {
        int p = p0 + tid;
        meds[tid]  = (p < PN) ? ts[(size_t)b * LN + p * 8 + 7] : 0.0f;
        sbias[tid] = bias[tid];
    }
    if (tid >= 128 && tid < 192)
        sdiv[tid - 128] = expf((float)(2 * (tid - 128)) * -0.07195578800731849f);

    float acc[2][4][4];
#pragma unroll
    for (int mf = 0; mf < 2; mf++)
#pragma unroll
        for (int nf = 0; nf < 4; nf++)
#pragma unroll
            for (int i = 0; i < 4; i++) acc[mf][nf][i] = 0.0f;

    const float* xbase = x + ((size_t)b * LN + (size_t)p0 * 8) * 32;
    const char*  gB    = (const char*)g_Bh;

    // A producer coords: 1024 float4 slots / 512 threads = 2 per thread
    const int ar = tid >> 3;     // 0..63 (row sub-index)
    const int aj = tid & 7;      // float4 within 32-float half

    float4 va[2];

    // READ-validity guard: the row for patch index PN is in-bounds for
    // chunks 0-3 and is needed (as row 128) by the shifted chunks 4-7.
#define LOAD_A(c_, h_)                                                        \
    do {                                                                      \
        _Pragma("unroll")                                                     \
        for (int it = 0; it < 2; it++) {                                      \
            int r = it * 64 + ar;                                             \
            va[it] = make_float4(0.f, 0.f, 0.f, 0.f);                         \
            if (p0 + r < PN + 1)                                              \
                va[it] = *(const float4*)(xbase + (size_t)r * 256 +           \
                                          (c_) * 64 + (h_) * 32 + aj * 4);    \
        }                                                                     \
    } while (0)

#define STS_A(buf_, h_)                                                       \
    do {                                                                      \
        _Pragma("unroll")                                                     \
        for (int it = 0; it < 2; it++) {                                      \
            int r = it * 64 + ar;                                             \
            uint32_t d = sbase + OFF_A + (buf_) * ABUF + r * AROW +           \
                         (h_) * 64 + aj * 8;                                  \
            uint32_t h0 = pack_h2(va[it].x, va[it].y);                        \
            uint32_t h1 = pack_h2(va[it].z, va[it].w);                        \
            asm volatile("st.shared.v2.b32 [%0], {%1,%2};"                    \
                         :: "r"(d), "r"(h0), "r"(h1));                        \
        }                                                                     \
    } while (0)

    // row 128 of tile c_ -> buffer buf_: 16 threads x one float4 (64 floats)
#define ROW128(c_, buf_)                                                      \
    do {                                                                      \
        if (tid < 16) {                                                       \
            float4 v = make_float4(0.f, 0.f, 0.f, 0.f);                       \
            if (p0 + 128 < PN + 1)                                            \
                v = *(const float4*)(xbase + (size_t)128 * 256 +              \
                                     (c_) * 64 + tid * 4);                    \
            uint32_t d = sbase + OFF_A + (buf_) * ABUF + 128 * AROW + tid * 8; \
            uint32_t h0 = pack_h2(v.x, v.y);                                  \
            uint32_t h1 = pack_h2(v.z, v.w);                                  \
            asm volatile("st.shared.v2.b32 [%0], {%1,%2};"                    \
                         :: "r"(d), "r"(h0), "r"(h1));                        \
        }                                                                     \
    } while (0)

    // B pair pp: chunk pp -> stage (pp&1)*2, chunk pp+4 -> stage (pp&1)*2+1.
    // One commit group per pair; 1024 16B slots per chunk / 512 threads.
#define CPASYNC_B_PAIR(pp_)                                                   \
    do {                                                                      \
        const int s0_ = ((pp_) & 1) * 2;                                      \
        _Pragma("unroll")                                                     \
        for (int i = 0; i < 2; i++) {                                         \
            int slot = i * 512 + tid;                                         \
            uint32_t d = sbase + OFF_B + s0_ * BTILE + slot * 16;             \
            const char* s = gB + (pp_) * 16384 + slot * 16;                   \
            asm volatile("cp.async.cg.shared.global [%0], [%1], 16;"          \
                         :: "r"(d), "l"(s));                                  \
        }                                                                     \
        _Pragma("unroll")                                                     \
        for (int i = 0; i < 2; i++) {                                         \
            int slot = i * 512 + tid;                                         \
            uint32_t d = sbase + OFF_B + (s0_ + 1) * BTILE + slot * 16;       \
            const char* s = gB + ((pp_) + 4) * 16384 + slot * 16;             \
            asm volatile("cp.async.cg.shared.global [%0], [%1], 16;"          \
                         :: "r"(d), "l"(s));                                  \
        }                                                                     \
        asm volatile("cp.async.commit_group;");                               \
    } while (0)

    // ---- prologue: B pairs 0,1 in flight; A tile 0 into buffer 0 ----
    CPASYNC_B_PAIR(0);
    CPASYNC_B_PAIR(1);
    LOAD_A(0, 0);
    STS_A(0, 0);
    LOAD_A(0, 1);
    STS_A(0, 1);
    ROW128(0, 0);

    const uint32_t aBase = sbase + OFF_A + (wm * 32 + g) * AROW + q * 4;
    const uint32_t bBase = sbase + OFF_B + (wn * 4) * 256 + lane * 8;

#define COMPUTE_KS(aB_, bB_, ks_)                                             \
    do {                                                                      \
        uint32_t a[2][4];                                                     \
        _Pragma("unroll")                                                     \
        for (int mf = 0; mf < 2; mf++) {                                      \
            uint32_t ad = (aB_) + mf * (16 * AROW) + (ks_) * 32;              \
            asm volatile("ld.shared.b32 %0, [%1];"       : "=r"(a[mf][0]) : "r"(ad)); \
            asm volatile("ld.shared.b32 %0, [%1+1152];"  : "=r"(a[mf][1]) : "r"(ad)); \
            asm volatile("ld.shared.b32 %0, [%1+16];"    : "=r"(a[mf][2]) : "r"(ad)); \
            asm volatile("ld.shared.b32 %0, [%1+1168];"  : "=r"(a[mf][3]) : "r"(ad)); \
        }                                                                     \
        _Pragma("unroll")                                                     \
        for (int nf = 0; nf < 4; nf++) {                                      \
            uint32_t b0, b1;                                                  \
            uint32_t bd = (bB_) + (ks_) * 4096 + nf * 256;                    \
            asm volatile("ld.shared.v2.b32 {%0,%1}, [%2];"                    \
                         : "=r"(b0), "=r"(b1) : "r"(bd));                     \
            _Pragma("unroll")                                                 \
            for (int mf = 0; mf < 2; mf++)                                    \
                mma_f16(acc[mf][nf], a[mf], b0, b1);                          \
        }                                                                     \
    } while (0)

#pragma unroll
    for (int p = 0; p < 4; p++) {
        // Retire pair p's B group before reading it.
        if (p == 0) asm volatile("cp.async.wait_group 1;" ::: "memory");
        else        asm volatile("cp.async.wait_group 0;" ::: "memory");
        __syncthreads();

        // Pair p+1's stages alias pair p-1, whose readers retired before the
        // barrier above -> safe to commit its replacement copy now.
        if (p >= 1 && p + 1 <= 3) CPASYNC_B_PAIR(p + 1);

        const int buf = p & 1;
        const uint32_t aB0 = aBase + buf * ABUF;          // chunk p: rows 0-127
        const uint32_t aB1 = aB0 + AROW;                  // chunk p+4: rows 1-128
        const uint32_t bB0 = bBase + ((p & 1) * 2) * BTILE;
        const uint32_t bB1 = bB0 + BTILE;
        const int nbuf = buf ^ 1;

        // ---- chunk p ----
        if (p < 3) LOAD_A(p + 1, 0);
        COMPUTE_KS(aB0, bB0, 0);
        COMPUTE_KS(aB0, bB0, 1);
        if (p < 3) STS_A(nbuf, 0);
        COMPUTE_KS(aB0, bB0, 2);
        COMPUTE_KS(aB0, bB0, 3);

        // ---- chunk p+4 (shifted rows of same tile) ----
        if (p < 3) LOAD_A(p + 1, 1);
        COMPUTE_KS(aB1, bB1, 0);
        COMPUTE_KS(aB1, bB1, 1);
        if (p < 3) {
            STS_A(nbuf, 1);
            ROW128(p + 1, nbuf);
        }
        COMPUTE_KS(aB1, bB1, 2);
        COMPUTE_KS(aB1, bB1, 3);
    }

    // ---- epilogue: + bias + positional encoding (fast sincos), write out ----
#pragma unroll
    for (int mf = 0; mf < 2; mf++) {
        int rr0 = wm * 32 + mf * 16 + g;
        int rr1 = rr0 + 8;
        float med0 = meds[rr0];
        float med1 = meds[rr1];
        bool ok0 = (p0 + rr0) < PN;
        bool ok1 = (p0 + rr1) < PN;
        size_t base0 = ((size_t)b * PN + (size_t)(p0 + rr0)) * DN;
        size_t base1 = ((size_t)b * PN + (size_t)(p0 + rr1)) * DN;
#pragma unroll
        for (int nf = 0; nf < 4; nf++) {
            int col = wn * 32 + nf * 8 + 2 * q;   // even
            float dv = sdiv[col >> 1];
            float bs0 = sbias[col];
            float bs1 = sbias[col + 1];
            float s, c;
            if (ok0) {
                __sincosf(med0 * dv, &s, &c);
                float2 v;
                v.x = acc[mf][nf][0] + bs0 + s;
                v.y = acc[mf][nf][1] + bs1 + c;
                *(float2*)(out + base0 + col) = v;
            }
            if (ok1) {
                __sincosf(med1 * dv, &s, &c);
                float2 v;
                v.x = acc[mf][nf][2] + bs0 + s;
                v.y = acc[mf][nf][3] + bs1 + c;
                *(float2*)(out + base1 + col) = v;
            }
        }
    }
}

extern "C" void kernel_launch(void* const* d_in, const int* in_sizes, int n_in,
                              void* d_out, int out_size) {
    const float* x    = (const float*)d_in[0];
    const float* ts   = (const float*)d_in[1];
    const float* w    = (const float*)d_in[2];
    const float* bias = (const float*)d_in[3];
    float* out = (float*)d_out;

    cudaFuncSetAttribute(patch_encoder_kernel,
                         cudaFuncAttributeMaxDynamicSharedMemorySize,
                         SMEM_TOTAL);

    pack_w_kernel<<<256, 256>>>(w);

    dim3 grid(32, BN);   // 32 patch-tiles x 32 batches
    patch_encoder_kernel<<<grid, 512, SMEM_TOTAL>>>(x, ts, bias, out);
}